// round 9
// baseline (speedup 1.0000x reference)
#include <cuda_runtime.h>
#include <cuda_bf16.h>
#include <cstdint>
#include <math.h>

#define NROW 4096
#define DIM  128
#define NSET 4
#define TOPK 16
#define PITCH 132   // floats per SMEM row (128 + 4 pad, conflict-free)

// ---------------- device scratch ----------------
__device__ float g_fn[NROW * DIM];
__device__ float g_nn[NSET * NROW * DIM];
__device__ float g_top[NSET * NROW * TOPK];
__device__ float g_partial[256];

// SMEM float offsets
#define OFF_A  0
#define OFF_B0 16896
#define OFF_B1 33792
#define OFF_T  50688
#define SMEM_BYTES 219136

__device__ __forceinline__ void cp16(unsigned int smem_dst, const float* gsrc) {
    asm volatile("cp.async.cg.shared.global [%0], [%1], 16;\n"
                 :: "r"(smem_dst), "l"(gsrc));
}
__device__ __forceinline__ void cp_commit() {
    asm volatile("cp.async.commit_group;\n");
}
template <int N>
__device__ __forceinline__ void cp_wait() {
    asm volatile("cp.async.wait_group %0;\n" :: "n"(N));
}

// ---------------- kernel 1: L2 normalize (one warp per row) ----------------
__global__ void __launch_bounds__(256) normalize_kernel(const float* __restrict__ f,
                                                        const float* __restrict__ negs) {
    int w    = blockIdx.x * 8 + (threadIdx.x >> 5);
    int lane = threadIdx.x & 31;
    const float* src;
    float* dst;
    if (w < NROW) {
        src = f + (size_t)w * DIM;
        dst = g_fn + (size_t)w * DIM;
    } else {
        int r = w - NROW;
        src = negs + (size_t)r * DIM;
        dst = g_nn + (size_t)r * DIM;
    }
    float4 v = ((const float4*)src)[lane];
    float ss = v.x * v.x + v.y * v.y + v.z * v.z + v.w * v.w;
#pragma unroll
    for (int off = 16; off > 0; off >>= 1)
        ss += __shfl_xor_sync(0xFFFFFFFFu, ss, off);
    float inv = 1.0f / fmaxf(sqrtf(ss), 1e-12f);
    v.x *= inv; v.y *= inv; v.z *= inv; v.w *= inv;
    ((float4*)dst)[lane] = v;
}

// ---------------- kernel 2: fused GEMM + mask + top-16 ----------------
// grid (32 rowblocks, 4 sets), block 256 (8 warps).
// CTA: 128 feature rows x 4096 neg cols. Warp: 16 rows x 128 cols per tile.
// A tile (128x128 fp32-as-tf32) SMEM-resident; B tiles double-buffered cp.async.
// Per-lane running sorted top-16 for rows (g) and (g+8); quad merge at end.
__global__ void __launch_bounds__(256, 1) fused_kernel(const int* __restrict__ targ,
                                                       const int* __restrict__ idxp) {
    extern __shared__ float smem[];
    float* As = smem + OFF_A;
    float* Bs[2] = { smem + OFF_B0, smem + OFF_B1 };
    int*   ts = (int*)(smem + OFF_T);

    int j     = blockIdx.y;
    int nbase = blockIdx.x * 128;
    int tid   = threadIdx.x;
    int wid   = tid >> 5;
    int lane  = tid & 31;
    int g     = lane >> 2;
    int c     = lane & 3;
    int wbase = wid * 16;

    const float* F  = g_fn + (size_t)nbase * DIM;
    const float* Nj = g_nn + (size_t)j * NROW * DIM;

    unsigned int sA  = (unsigned int)__cvta_generic_to_shared(As);
    unsigned int sB0 = (unsigned int)__cvta_generic_to_shared(Bs[0]);
    unsigned int sB1 = (unsigned int)__cvta_generic_to_shared(Bs[1]);
    unsigned int sBu[2] = { sB0, sB1 };

    // targets into SMEM
    for (int i = tid; i < NROW; i += 256) ts[i] = targ[i];

    // prologue: A tile + B tile 0 (group 0)
    for (int i = tid; i < 4096; i += 256) {
        int row = i >> 5, ch = i & 31;
        cp16(sA  + (row * PITCH + ch * 4) * 4, F  + (size_t)row * DIM + ch * 4);
        cp16(sB0 + (row * PITCH + ch * 4) * 4, Nj + (size_t)row * DIM + ch * 4);
    }
    cp_commit();
    cp_wait<0>();
    __syncthreads();

    bool domask = (j == *idxp);
    int  tn0 = ts[nbase + wbase + g];
    int  tn1 = ts[nbase + wbase + g + 8];

    // running top-16 for the two rows this lane co-owns
    float t0[TOPK], t1[TOPK];
#pragma unroll
    for (int s = 0; s < TOPK; ++s) { t0[s] = -INFINITY; t1[s] = -INFINITY; }

    const float* Arow0 = As + (wbase + g) * PITCH;
    const float* Arow1 = As + (wbase + g + 8) * PITCH;

#pragma unroll 1
    for (int t = 0; t < 32; ++t) {
        // prefetch next B tile
        if (t < 31) {
            unsigned int dst = sBu[(t + 1) & 1];
            const float* src = Nj + (size_t)(t + 1) * 128 * DIM;
            for (int i = tid; i < 4096; i += 256) {
                int row = i >> 5, ch = i & 31;
                cp16(dst + (row * PITCH + ch * 4) * 4, src + (size_t)row * DIM + ch * 4);
            }
            cp_commit();
            cp_wait<1>();
        } else {
            cp_wait<0>();
        }
        __syncthreads();

        const float* B = Bs[t & 1] + g * PITCH + c;

        float acc[16][4];
#pragma unroll
        for (int ni = 0; ni < 16; ++ni)
#pragma unroll
            for (int r = 0; r < 4; ++r) acc[ni][r] = 0.0f;

#pragma unroll
        for (int kk8 = 0; kk8 < 16; ++kk8) {
            int k0 = kk8 * 8;
            unsigned int a0 = __float_as_uint(Arow0[k0 + c]);
            unsigned int a1 = __float_as_uint(Arow1[k0 + c]);
            unsigned int a2 = __float_as_uint(Arow0[k0 + c + 4]);
            unsigned int a3 = __float_as_uint(Arow1[k0 + c + 4]);
#pragma unroll
            for (int ni = 0; ni < 16; ++ni) {
                unsigned int b0 = __float_as_uint(B[ni * 8 * PITCH + k0]);
                unsigned int b1 = __float_as_uint(B[ni * 8 * PITCH + k0 + 4]);
                asm volatile(
                    "mma.sync.aligned.m16n8k8.row.col.f32.tf32.tf32.f32 "
                    "{%0,%1,%2,%3}, {%4,%5,%6,%7}, {%8,%9}, {%0,%1,%2,%3};"
                    : "+f"(acc[ni][0]), "+f"(acc[ni][1]),
                      "+f"(acc[ni][2]), "+f"(acc[ni][3])
                    : "r"(a0), "r"(a1), "r"(a2), "r"(a3),
                      "r"(b0), "r"(b1));
            }
        }

        // top-k insert for this tile
        int colbase = t * 128;
#pragma unroll
        for (int ni = 0; ni < 16; ++ni) {
            int col0 = colbase + ni * 8 + 2 * c;
            float v0 = acc[ni][0], v1 = acc[ni][1];   // row g
            float v2 = acc[ni][2], v3 = acc[ni][3];   // row g+8
            if (domask) {
                int tc0 = ts[col0], tc1 = ts[col0 + 1];
                if (tn0 == tc0) v0 = -1e9f;
                if (tn0 == tc1) v1 = -1e9f;
                if (tn1 == tc0) v2 = -1e9f;
                if (tn1 == tc1) v3 = -1e9f;
            }
            if (v0 > t0[TOPK - 1]) {
#pragma unroll
                for (int s = TOPK - 1; s >= 1; --s)
                    t0[s] = (v0 > t0[s]) ? ((v0 > t0[s - 1]) ? t0[s - 1] : v0) : t0[s];
                t0[0] = fmaxf(t0[0], v0);
            }
            if (v1 > t0[TOPK - 1]) {
#pragma unroll
                for (int s = TOPK - 1; s >= 1; --s)
                    t0[s] = (v1 > t0[s]) ? ((v1 > t0[s - 1]) ? t0[s - 1] : v1) : t0[s];
                t0[0] = fmaxf(t0[0], v1);
            }
            if (v2 > t1[TOPK - 1]) {
#pragma unroll
                for (int s = TOPK - 1; s >= 1; --s)
                    t1[s] = (v2 > t1[s]) ? ((v2 > t1[s - 1]) ? t1[s - 1] : v2) : t1[s];
                t1[0] = fmaxf(t1[0], v2);
            }
            if (v3 > t1[TOPK - 1]) {
#pragma unroll
                for (int s = TOPK - 1; s >= 1; --s)
                    t1[s] = (v3 > t1[s]) ? ((v3 > t1[s - 1]) ? t1[s - 1] : v3) : t1[s];
                t1[0] = fmaxf(t1[0], v3);
            }
        }
        __syncthreads();
    }

    // ---- quad merge (lanes c=0..3 share each row) + store ----
    unsigned int quadmask = 0xFu << (lane & ~3);
    int r0 = nbase + wbase + g;
    int r1 = nbase + wbase + g + 8;

#pragma unroll 1
    for (int it = 0; it < TOPK; ++it) {
        float m = t0[0];
        m = fmaxf(m, __shfl_xor_sync(0xFFFFFFFFu, m, 1));
        m = fmaxf(m, __shfl_xor_sync(0xFFFFFFFFu, m, 2));
        unsigned bal = __ballot_sync(0xFFFFFFFFu, t0[0] == m);
        int winner = __ffs(bal & quadmask) - 1;
        if (lane == winner) {
#pragma unroll
            for (int s = 0; s < TOPK - 1; ++s) t0[s] = t0[s + 1];
            t0[TOPK - 1] = -INFINITY;
        }
        if (c == 0) g_top[((size_t)j * NROW + r0) * TOPK + it] = m;
    }
#pragma unroll 1
    for (int it = 0; it < TOPK; ++it) {
        float m = t1[0];
        m = fmaxf(m, __shfl_xor_sync(0xFFFFFFFFu, m, 1));
        m = fmaxf(m, __shfl_xor_sync(0xFFFFFFFFu, m, 2));
        unsigned bal = __ballot_sync(0xFFFFFFFFu, t1[0] == m);
        int winner = __ffs(bal & quadmask) - 1;
        if (lane == winner) {
#pragma unroll
            for (int s = 0; s < TOPK - 1; ++s) t1[s] = t1[s + 1];
            t1[TOPK - 1] = -INFINITY;
        }
        if (c == 0) g_top[((size_t)j * NROW + r1) * TOPK + it] = m;
    }
}

// ---------------- kernel 3: entropy + weighted partial reduction ----------------
__global__ void __launch_bounds__(256) entropy_kernel() {
    __shared__ float red[256];
    int t = blockIdx.x * 256 + threadIdx.x;
    int n = t >> 4;
    int k = t & 15;

    float l[NSET];
#pragma unroll
    for (int j = 0; j < NSET; ++j)
        l[j] = g_top[((size_t)j * NROW + n) * TOPK + k] * 100.0f;

    float mx = l[0];
#pragma unroll
    for (int j = 1; j < NSET; ++j) mx = fmaxf(mx, l[j]);
    float e[NSET], s = 0.0f;
#pragma unroll
    for (int j = 0; j < NSET; ++j) { e[j] = expf(l[j] - mx); s += e[j]; }
    float ls  = logf(s);
    float ent = 0.0f;
#pragma unroll
    for (int j = 0; j < NSET; ++j) {
        float lp = l[j] - mx - ls;
        ent += (e[j] / s) * lp;
    }

    float dsum = (1.0f - powf(0.95f, 16.0f)) / 0.05f;
    float wk   = powf(0.95f, (float)k) / dsum;

    red[threadIdx.x] = ent * wk;
    __syncthreads();
#pragma unroll
    for (int off = 128; off > 0; off >>= 1) {
        if (threadIdx.x < off) red[threadIdx.x] += red[threadIdx.x + off];
        __syncthreads();
    }
    if (threadIdx.x == 0) g_partial[blockIdx.x] = red[0];
}

// ---------------- kernel 4: final reduce ----------------
__global__ void __launch_bounds__(256) finalize_kernel(float* __restrict__ out) {
    __shared__ float red[256];
    red[threadIdx.x] = g_partial[threadIdx.x];
    __syncthreads();
#pragma unroll
    for (int off = 128; off > 0; off >>= 1) {
        if (threadIdx.x < off) red[threadIdx.x] += red[threadIdx.x + off];
        __syncthreads();
    }
    if (threadIdx.x == 0)
        out[0] = red[0] / (float)NROW + logf((float)NSET);
}

// ---------------- launch ----------------
extern "C" void kernel_launch(void* const* d_in, const int* in_sizes, int n_in,
                              void* d_out, int out_size) {
    const float* feature = (const float*)d_in[0];
    const int*   target  = (const int*)d_in[1];
    const float* negs    = (const float*)d_in[2];
    const int*   idxp    = (const int*)d_in[3];
    float*       out     = (float*)d_out;

    cudaFuncSetAttribute(fused_kernel,
                         cudaFuncAttributeMaxDynamicSharedMemorySize, SMEM_BYTES);

    normalize_kernel<<<(NROW + NSET * NROW) / 8, 256>>>(feature, negs);

    dim3 fgrid(NROW / 128, NSET);
    fused_kernel<<<fgrid, 256, SMEM_BYTES>>>(target, idxp);

    entropy_kernel<<<256, 256>>>();

    finalize_kernel<<<1, 256>>>(out);
}